// round 10
// baseline (speedup 1.0000x reference)
#include <cuda_runtime.h>
#include <cuda_bf16.h>
#include <cstdint>
#include <math.h>

#define N_NODES 100000
#define NFEAT   512
#define NHID    256
#define NCLASS  40
#define NEDGE   1600000
#define KHOPS   10
#define ALPHA_F 0.1f

// ---------------- scratch (device globals; no allocs allowed) ----------------
__device__ __nv_bfloat16  g_hb [(size_t)N_NODES * NHID];   // 51.2 MB (bf16 h)
__device__ float          g_h2 [(size_t)N_NODES * NCLASS]; // 16 MB
__device__ float          g_za [(size_t)N_NODES * NCLASS]; // 16 MB
__device__ __nv_bfloat16  g_xb [(size_t)N_NODES * NFEAT];  // 102.4 MB (bf16 x)
__device__ __nv_bfloat16  g_w1b[(size_t)NHID * NFEAT];     // 256 KB (W1^T bf16 [N][K])
__device__ __nv_bfloat16  g_w2t[(size_t)NCLASS * NHID];    // 20 KB (W2^T bf16 [N][K])
__device__ int   g_deg[N_NODES];
__device__ int   g_rowptr[N_NODES + 1];
__device__ int   g_cursor[N_NODES];
__device__ int2  g_cedge[NEDGE];                           // 12.8 MB {src, val bits}

// ---------------- cp.async helpers ----------------
__device__ __forceinline__ void cp_async16(uint32_t saddr, const void* gaddr) {
    asm volatile("cp.async.cg.shared.global [%0], [%1], 16;\n" :: "r"(saddr), "l"(gaddr));
}
__device__ __forceinline__ void cp_commit() {
    asm volatile("cp.async.commit_group;\n" ::: "memory");
}
__device__ __forceinline__ void cp_wait1() {
    asm volatile("cp.async.wait_group 1;\n" ::: "memory");
}
__device__ __forceinline__ void ldsm_x4(uint32_t& r0, uint32_t& r1, uint32_t& r2,
                                        uint32_t& r3, uint32_t addr) {
    asm volatile("ldmatrix.sync.aligned.m8n8.x4.shared.b16 {%0,%1,%2,%3}, [%4];"
                 : "=r"(r0), "=r"(r1), "=r"(r2), "=r"(r3) : "r"(addr));
}

// ---------------- bf16 conversions ----------------
__global__ void __launch_bounds__(256)
conv_x_kernel(const float* __restrict__ x, __nv_bfloat16* __restrict__ xb)
{
    int i = blockIdx.x * 256 + threadIdx.x;         // per 8 floats
    const int n8 = N_NODES * NFEAT / 8;
    if (i < n8) {
        float4 a = ((const float4*)x)[2 * i];
        float4 b = ((const float4*)x)[2 * i + 1];
        __nv_bfloat162 p0 = __floats2bfloat162_rn(a.x, a.y);
        __nv_bfloat162 p1 = __floats2bfloat162_rn(a.z, a.w);
        __nv_bfloat162 p2 = __floats2bfloat162_rn(b.x, b.y);
        __nv_bfloat162 p3 = __floats2bfloat162_rn(b.z, b.w);
        uint4 o;
        o.x = *reinterpret_cast<unsigned*>(&p0);
        o.y = *reinterpret_cast<unsigned*>(&p1);
        o.z = *reinterpret_cast<unsigned*>(&p2);
        o.w = *reinterpret_cast<unsigned*>(&p3);
        ((uint4*)xb)[i] = o;
    }
}

__global__ void __launch_bounds__(256)
conv_w1_kernel(const float* __restrict__ W1, __nv_bfloat16* __restrict__ w1b)
{
    int id = blockIdx.x * 256 + threadIdx.x;        // (n,k), k fast
    if (id < NHID * NFEAT) {
        int n = id >> 9;
        int k = id & 511;
        w1b[id] = __float2bfloat16(W1[(size_t)k * NHID + n]);
    }
}

__global__ void __launch_bounds__(256)
conv_w2_kernel(const float* __restrict__ W2, __nv_bfloat16* __restrict__ w2t)
{
    int id = blockIdx.x * 256 + threadIdx.x;        // (n,k), k fast
    if (id < NCLASS * NHID) {
        int n = id >> 8;
        int k = id & 255;
        w2t[id] = __float2bfloat16(W2[(size_t)k * NCLASS + n]);
    }
}

// ---------------- GEMM1: hb = relu(x @ W1 + b1) via bf16 mma.sync + ldmatrix -
#define G1_BK  32
#define G1_STR 40

__global__ void __launch_bounds__(256, 2)
gemm1_bf16_kernel(const __nv_bfloat16* __restrict__ xb,
                  const __nv_bfloat16* __restrict__ w1b,
                  const float* __restrict__ b1, __nv_bfloat16* __restrict__ hb)
{
    __shared__ __nv_bfloat16 As[2][128][G1_STR];
    __shared__ __nv_bfloat16 Bs[2][128][G1_STR];

    const int tid  = threadIdx.x;
    const int warp = tid >> 5;
    const int lane = tid & 31;
    const int grp  = lane >> 2;
    const int tig  = lane & 3;
    const int warp_m = warp & 1;
    const int warp_n = warp >> 1;

    const int m0 = blockIdx.x * 128;
    const int n0 = blockIdx.y * 128;

    const uint32_t sA = (uint32_t)__cvta_generic_to_shared(&As[0][0][0]);
    const uint32_t sB = (uint32_t)__cvta_generic_to_shared(&Bs[0][0][0]);
    const uint32_t BUFB = 128u * G1_STR * 2u;

    // ldmatrix per-thread row/col selectors
    const int lm_row = lane & 15;        // row within 16-row group
    const int lm_kof = (lane >> 4) * 8;  // 0 or 8 (k offset)

    float acc[4][4][4];
    #pragma unroll
    for (int i = 0; i < 4; i++)
        #pragma unroll
        for (int j = 0; j < 4; j++)
            #pragma unroll
            for (int r = 0; r < 4; r++) acc[i][j][r] = 0.f;

    const int c0 = tid, c1 = tid + 256;
    const int ar0 = c0 >> 2, ak0 = (c0 & 3) * 8;
    const int ar1 = c1 >> 2, ak1 = (c1 & 3) * 8;
    const int gr0 = min(m0 + ar0, N_NODES - 1);
    const int gr1 = min(m0 + ar1, N_NODES - 1);

    const int NT = NFEAT / G1_BK;  // 16

    auto load_tile = [&](int kt, int b) {
        const int kb = kt * G1_BK;
        const uint32_t ab = sA + (uint32_t)b * BUFB;
        const uint32_t bb = sB + (uint32_t)b * BUFB;
        cp_async16(ab + (uint32_t)((ar0 * G1_STR + ak0) * 2),
                   xb + (size_t)gr0 * NFEAT + kb + ak0);
        cp_async16(ab + (uint32_t)((ar1 * G1_STR + ak1) * 2),
                   xb + (size_t)gr1 * NFEAT + kb + ak1);
        cp_async16(bb + (uint32_t)((ar0 * G1_STR + ak0) * 2),
                   w1b + (size_t)(n0 + ar0) * NFEAT + kb + ak0);
        cp_async16(bb + (uint32_t)((ar1 * G1_STR + ak1) * 2),
                   w1b + (size_t)(n0 + ar1) * NFEAT + kb + ak1);
    };

    load_tile(0, 0);
    cp_commit();

    for (int kt = 0; kt < NT; kt++) {
        if (kt + 1 < NT) load_tile(kt + 1, (kt + 1) & 1);
        cp_commit();
        cp_wait1();
        __syncthreads();

        const int buf = kt & 1;
        const uint32_t abuf = sA + (uint32_t)buf * BUFB;
        const uint32_t bbuf = sB + (uint32_t)buf * BUFB;
        #pragma unroll
        for (int ks = 0; ks < 2; ks++) {
            const int kb = ks * 16 + lm_kof;
            uint32_t a[4][4], b[4][2];
            // A: 4 x ldmatrix.x4 (rows r..r+15, k kb..kb+15)
            #pragma unroll
            for (int mf = 0; mf < 4; mf++) {
                const int r = warp_m * 64 + mf * 16 + lm_row;
                ldsm_x4(a[mf][0], a[mf][1], a[mf][2], a[mf][3],
                        abuf + (uint32_t)((r * G1_STR + kb) * 2));
            }
            // B: 2 x ldmatrix.x4, each covers an nf pair
            #pragma unroll
            for (int np = 0; np < 2; np++) {
                const int cn = warp_n * 32 + np * 16 + lm_row;
                ldsm_x4(b[2*np][0], b[2*np + 1][0], b[2*np][1], b[2*np + 1][1],
                        bbuf + (uint32_t)((cn * G1_STR + kb) * 2));
            }
            #pragma unroll
            for (int mf = 0; mf < 4; mf++)
                #pragma unroll
                for (int nf = 0; nf < 4; nf++) {
                    asm volatile(
                        "mma.sync.aligned.m16n8k16.row.col.f32.bf16.bf16.f32 "
                        "{%0,%1,%2,%3}, {%4,%5,%6,%7}, {%8,%9}, {%0,%1,%2,%3};\n"
                        : "+f"(acc[mf][nf][0]), "+f"(acc[mf][nf][1]),
                          "+f"(acc[mf][nf][2]), "+f"(acc[mf][nf][3])
                        : "r"(a[mf][0]), "r"(a[mf][1]), "r"(a[mf][2]), "r"(a[mf][3]),
                          "r"(b[nf][0]), "r"(b[nf][1]));
                }
        }
        __syncthreads();
    }

    // epilogue: bias + relu, bf16x2 stores
    #pragma unroll
    for (int nf = 0; nf < 4; nf++) {
        const int cg = n0 + warp_n * 32 + nf * 8 + 2 * tig;
        const float bx = b1[cg], by = b1[cg + 1];
        #pragma unroll
        for (int mf = 0; mf < 4; mf++) {
            const int rg = m0 + warp_m * 64 + mf * 16 + grp;
            if (rg < N_NODES) {
                __nv_bfloat162 o = __floats2bfloat162_rn(
                    fmaxf(acc[mf][nf][0] + bx, 0.f),
                    fmaxf(acc[mf][nf][1] + by, 0.f));
                *(uint32_t*)&hb[(size_t)rg * NHID + cg] = *reinterpret_cast<uint32_t*>(&o);
            }
            if (rg + 8 < N_NODES) {
                __nv_bfloat162 o = __floats2bfloat162_rn(
                    fmaxf(acc[mf][nf][2] + bx, 0.f),
                    fmaxf(acc[mf][nf][3] + by, 0.f));
                *(uint32_t*)&hb[(size_t)(rg + 8) * NHID + cg] = *reinterpret_cast<uint32_t*>(&o);
            }
        }
    }
}

// ---------------- GEMM2: h2 = hb @ W2 + b2 via bf16 mma.sync -----------------
#define G2_ASTR 24
#define G2_BSTR 264

__global__ void __launch_bounds__(128)
gemm2_bf16_kernel(const __nv_bfloat16* __restrict__ hb,
                  const __nv_bfloat16* __restrict__ w2t,
                  const float* __restrict__ b2, float* __restrict__ h2)
{
    __shared__ __nv_bfloat16 As[2][256][G2_ASTR];
    __shared__ __nv_bfloat16 Bs[NCLASS][G2_BSTR];

    const int tid  = threadIdx.x;
    const int warp = tid >> 5;
    const int lane = tid & 31;
    const int grp  = lane >> 2;
    const int tig  = lane & 3;

    const int r0 = blockIdx.x * 256;

    const uint32_t sA = (uint32_t)__cvta_generic_to_shared(&As[0][0][0]);
    const uint32_t ABUF = 256u * G2_ASTR * 2u;

    #pragma unroll
    for (int i = 0; i < 10; i++) {
        int c = tid + i * 128;
        int n = c >> 5;
        int ks = (c & 31) * 8;
        *(uint4*)&Bs[n][ks] = *(const uint4*)&w2t[(size_t)n * NHID + ks];
    }

    float acc[4][5][4];
    #pragma unroll
    for (int i = 0; i < 4; i++)
        #pragma unroll
        for (int j = 0; j < 5; j++)
            #pragma unroll
            for (int r = 0; r < 4; r++) acc[i][j][r] = 0.f;

    const int NT = NHID / 16;   // 16
    auto load_tile = [&](int kt, int b) {
        const uint32_t ab = sA + (uint32_t)b * ABUF;
        #pragma unroll
        for (int i = 0; i < 4; i++) {
            int c = tid + i * 128;
            int row = c >> 1;
            int seg = (c & 1) * 8;
            int gr = min(r0 + row, N_NODES - 1);
            cp_async16(ab + (uint32_t)((row * G2_ASTR + seg) * 2),
                       hb + (size_t)gr * NHID + kt * 16 + seg);
        }
    };

    load_tile(0, 0);
    cp_commit();
    __syncthreads();

    for (int kt = 0; kt < NT; kt++) {
        if (kt + 1 < NT) load_tile(kt + 1, (kt + 1) & 1);
        cp_commit();
        cp_wait1();
        __syncthreads();

        const int buf = kt & 1;
        uint32_t a[4][4], b[5][2];
        #pragma unroll
        for (int mf = 0; mf < 4; mf++) {
            const int r = warp * 64 + mf * 16 + grp;
            a[mf][0] = *(const uint32_t*)&As[buf][r    ][tig * 2    ];
            a[mf][1] = *(const uint32_t*)&As[buf][r + 8][tig * 2    ];
            a[mf][2] = *(const uint32_t*)&As[buf][r    ][tig * 2 + 8];
            a[mf][3] = *(const uint32_t*)&As[buf][r + 8][tig * 2 + 8];
        }
        #pragma unroll
        for (int nf = 0; nf < 5; nf++) {
            const int cn = nf * 8 + grp;
            b[nf][0] = *(const uint32_t*)&Bs[cn][kt * 16 + tig * 2    ];
            b[nf][1] = *(const uint32_t*)&Bs[cn][kt * 16 + tig * 2 + 8];
        }
        #pragma unroll
        for (int mf = 0; mf < 4; mf++)
            #pragma unroll
            for (int nf = 0; nf < 5; nf++) {
                asm volatile(
                    "mma.sync.aligned.m16n8k16.row.col.f32.bf16.bf16.f32 "
                    "{%0,%1,%2,%3}, {%4,%5,%6,%7}, {%8,%9}, {%0,%1,%2,%3};\n"
                    : "+f"(acc[mf][nf][0]), "+f"(acc[mf][nf][1]),
                      "+f"(acc[mf][nf][2]), "+f"(acc[mf][nf][3])
                    : "r"(a[mf][0]), "r"(a[mf][1]), "r"(a[mf][2]), "r"(a[mf][3]),
                      "r"(b[nf][0]), "r"(b[nf][1]));
            }
        __syncthreads();
    }

    #pragma unroll
    for (int nf = 0; nf < 5; nf++) {
        const int col = nf * 8 + 2 * tig;
        const float bx = b2[col], by = b2[col + 1];
        #pragma unroll
        for (int mf = 0; mf < 4; mf++) {
            const int rg = r0 + warp * 64 + mf * 16 + grp;
            if (rg < N_NODES) {
                float2 o;
                o.x = acc[mf][nf][0] + bx;
                o.y = acc[mf][nf][1] + by;
                *(float2*)&h2[(size_t)rg * NCLASS + col] = o;
            }
            if (rg + 8 < N_NODES) {
                float2 o;
                o.x = acc[mf][nf][2] + bx;
                o.y = acc[mf][nf][3] + by;
                *(float2*)&h2[(size_t)(rg + 8) * NCLASS + col] = o;
            }
        }
    }
}

// ================= CSR build (by dst), rebuilt deterministically each call ===
__global__ void __launch_bounds__(256)
zero_deg_kernel(int* __restrict__ deg)
{
    int i = blockIdx.x * 256 + threadIdx.x;
    if (i < N_NODES) deg[i] = 0;
}

__global__ void __launch_bounds__(256)
hist_kernel(const int* __restrict__ edst, int* __restrict__ deg)
{
    int e = blockIdx.x * 256 + threadIdx.x;
    if (e < NEDGE) atomicAdd(&deg[edst[e]], 1);
}

__global__ void __launch_bounds__(1024)
scan_kernel(const int* __restrict__ deg, int* __restrict__ rowptr,
            int* __restrict__ cursor)
{
    __shared__ int part[1024];
    const int tid = threadIdx.x;
    const int CH = (N_NODES + 1023) / 1024;   // 98
    const int base = tid * CH;

    int s = 0;
    for (int i = 0; i < CH; i++) {
        int idx = base + i;
        if (idx < N_NODES) s += deg[idx];
    }
    part[tid] = s;
    __syncthreads();
    for (int off = 1; off < 1024; off <<= 1) {
        int v = (tid >= off) ? part[tid - off] : 0;
        __syncthreads();
        part[tid] += v;
        __syncthreads();
    }
    int run = (tid > 0) ? part[tid - 1] : 0;
    for (int i = 0; i < CH; i++) {
        int idx = base + i;
        if (idx < N_NODES) {
            rowptr[idx] = run;
            cursor[idx] = run;
            run += deg[idx];
        }
    }
    if (tid == 1023) rowptr[N_NODES] = run;
}

__global__ void __launch_bounds__(256)
scatter_kernel(const int* __restrict__ esrc, const int* __restrict__ edst,
               const float* __restrict__ eval_, int* __restrict__ cursor,
               int2* __restrict__ cedge)
{
    int e = blockIdx.x * 256 + threadIdx.x;
    if (e < NEDGE) {
        int d = edst[e];
        int slot = atomicAdd(&cursor[d], 1);
        cedge[slot] = make_int2(esrc[e],
                                __float_as_int((1.0f - ALPHA_F) * eval_[e]));
    }
}

// ======== propagation hop: zout[dst] = alpha*h2[dst] + sum ev*zin[src] =======
__global__ void __launch_bounds__(256)
prop_kernel(const int* __restrict__ rowptr, const int2* __restrict__ cedge,
            const float* __restrict__ h2,
            const float* __restrict__ zin, float* __restrict__ zout)
{
    int idx = blockIdx.x * 256 + threadIdx.x;
    if (idx >= N_NODES * 10) return;
    int dst = idx / 10;
    int g = idx - dst * 10;
    const int col = g * 4;

    int e  = rowptr[dst];
    int e1 = rowptr[dst + 1];

    float4 hv = *(const float4*)&h2[(size_t)dst * NCLASS + col];
    float4 acc0 = make_float4(ALPHA_F * hv.x, ALPHA_F * hv.y,
                              ALPHA_F * hv.z, ALPHA_F * hv.w);
    float4 acc1 = make_float4(0.f, 0.f, 0.f, 0.f);

    for (; e + 4 <= e1; e += 4) {
        int2 d0 = cedge[e], d1 = cedge[e + 1], d2 = cedge[e + 2], d3 = cedge[e + 3];
        float v0 = __int_as_float(d0.y), v1 = __int_as_float(d1.y);
        float v2 = __int_as_float(d2.y), v3 = __int_as_float(d3.y);
        float4 z0 = __ldg((const float4*)&zin[(size_t)d0.x * NCLASS + col]);
        float4 z1 = __ldg((const float4*)&zin[(size_t)d1.x * NCLASS + col]);
        float4 z2 = __ldg((const float4*)&zin[(size_t)d2.x * NCLASS + col]);
        float4 z3 = __ldg((const float4*)&zin[(size_t)d3.x * NCLASS + col]);
        acc0.x = fmaf(v0, z0.x, acc0.x); acc0.y = fmaf(v0, z0.y, acc0.y);
        acc0.z = fmaf(v0, z0.z, acc0.z); acc0.w = fmaf(v0, z0.w, acc0.w);
        acc1.x = fmaf(v1, z1.x, acc1.x); acc1.y = fmaf(v1, z1.y, acc1.y);
        acc1.z = fmaf(v1, z1.z, acc1.z); acc1.w = fmaf(v1, z1.w, acc1.w);
        acc0.x = fmaf(v2, z2.x, acc0.x); acc0.y = fmaf(v2, z2.y, acc0.y);
        acc0.z = fmaf(v2, z2.z, acc0.z); acc0.w = fmaf(v2, z2.w, acc0.w);
        acc1.x = fmaf(v3, z3.x, acc1.x); acc1.y = fmaf(v3, z3.y, acc1.y);
        acc1.z = fmaf(v3, z3.z, acc1.z); acc1.w = fmaf(v3, z3.w, acc1.w);
    }
    for (; e < e1; e++) {
        int2 d0 = cedge[e];
        float v0 = __int_as_float(d0.y);
        float4 z0 = __ldg((const float4*)&zin[(size_t)d0.x * NCLASS + col]);
        acc0.x = fmaf(v0, z0.x, acc0.x); acc0.y = fmaf(v0, z0.y, acc0.y);
        acc0.z = fmaf(v0, z0.z, acc0.z); acc0.w = fmaf(v0, z0.w, acc0.w);
    }
    acc0.x += acc1.x; acc0.y += acc1.y; acc0.z += acc1.z; acc0.w += acc1.w;
    *(float4*)&zout[(size_t)dst * NCLASS + col] = acc0;
}

// ---------------- log_softmax per row ----------------
__global__ void __launch_bounds__(256)
softmax_kernel(const float* __restrict__ z, float* __restrict__ out)
{
    int row = blockIdx.x * 8 + (threadIdx.x >> 5);
    int lane = threadIdx.x & 31;
    if (row >= N_NODES) return;
    const float* zr = z + (size_t)row * NCLASS;
    float v0 = zr[lane];
    bool has2 = (lane + 32) < NCLASS;
    float v1 = has2 ? zr[lane + 32] : -3.402823466e38f;
    float m = fmaxf(v0, v1);
    #pragma unroll
    for (int o = 16; o > 0; o >>= 1) m = fmaxf(m, __shfl_xor_sync(0xffffffffu, m, o));
    float s = __expf(v0 - m) + (has2 ? __expf(v1 - m) : 0.f);
    #pragma unroll
    for (int o = 16; o > 0; o >>= 1) s += __shfl_xor_sync(0xffffffffu, s, o);
    float lse = m + __logf(s);
    float* orow = out + (size_t)row * NCLASS;
    orow[lane] = v0 - lse;
    if (has2) orow[lane + 32] = v1 - lse;
}

// ---------------- launch ----------------
extern "C" void kernel_launch(void* const* d_in, const int* in_sizes, int n_in,
                              void* d_out, int out_size)
{
    const float* x     = (const float*)d_in[0];
    const int*   esrc  = (const int*)  d_in[1];
    const int*   edst  = (const int*)  d_in[2];
    const float* eval_ = (const float*)d_in[3];
    const float* W1    = (const float*)d_in[4];
    const float* b1    = (const float*)d_in[5];
    const float* W2    = (const float*)d_in[6];
    const float* b2    = (const float*)d_in[7];
    float* out = (float*)d_out;

    float *h2, *za;
    __nv_bfloat16 *hb, *xb, *w1b, *w2t;
    int *deg, *rowptr, *cursor;
    int2 *cedge;
    cudaGetSymbolAddress((void**)&hb,     g_hb);
    cudaGetSymbolAddress((void**)&h2,     g_h2);
    cudaGetSymbolAddress((void**)&za,     g_za);
    cudaGetSymbolAddress((void**)&xb,     g_xb);
    cudaGetSymbolAddress((void**)&w1b,    g_w1b);
    cudaGetSymbolAddress((void**)&w2t,    g_w2t);
    cudaGetSymbolAddress((void**)&deg,    g_deg);
    cudaGetSymbolAddress((void**)&rowptr, g_rowptr);
    cudaGetSymbolAddress((void**)&cursor, g_cursor);
    cudaGetSymbolAddress((void**)&cedge,  g_cedge);

    // bf16 conversions
    conv_x_kernel<<<(N_NODES * NFEAT / 8 + 255) / 256, 256>>>(x, xb);
    conv_w1_kernel<<<(NHID * NFEAT + 255) / 256, 256>>>(W1, w1b);
    conv_w2_kernel<<<(NCLASS * NHID + 255) / 256, 256>>>(W2, w2t);

    // GEMM1 (bf16 mma.sync + ldmatrix) -> hb (bf16)
    dim3 g1((N_NODES + 127) / 128, NHID / 128);   // (782, 2)
    gemm1_bf16_kernel<<<g1, 256>>>(xb, w1b, b1, hb);

    // GEMM2 (bf16 mma.sync) -> h2 (fp32)
    gemm2_bf16_kernel<<<(N_NODES + 255) / 256, 128>>>(hb, w2t, b2, h2);

    // CSR build
    zero_deg_kernel<<<(N_NODES + 255) / 256, 256>>>(deg);
    hist_kernel<<<(NEDGE + 255) / 256, 256>>>(edst, deg);
    scan_kernel<<<1, 1024>>>(deg, rowptr, cursor);
    scatter_kernel<<<(NEDGE + 255) / 256, 256>>>(esrc, edst, eval_, cursor, cedge);

    const int prop_blocks = (N_NODES * 10 + 255) / 256;
    const float* zin = h2;
    for (int i = 0; i < KHOPS; i++) {
        float* zout = (i % 2 == 0) ? za : out;   // last iter (i=9) writes `out`
        prop_kernel<<<prop_blocks, 256>>>(rowptr, cedge, h2, zin, zout);
        zin = zout;
    }

    softmax_kernel<<<(N_NODES + 7) / 8, 256>>>(out, out);
}